// round 4
// baseline (speedup 1.0000x reference)
#include <cuda_runtime.h>
#include <math.h>

#define NPTS 1024
#define H 128
#define TROWS 1536
#define TRI_TOTAL ((NPTS * (NPTS + 1)) / 2)   // 524800

// Scratch (device globals; no allocation allowed)
__device__ float  g_table[TROWS * H];   // g_o((row-1)*0.1), W and b folded in
__device__ float  g_WT[H * H];          // W transposed: WT[h][o]
__device__ float4 g_pts[NPTS];          // (x, y, z, |p|^2)

// ---------------------------------------------------------------------------
// Prep: pack points with squared norm; transpose W for coalesced table build.
// ---------------------------------------------------------------------------
__global__ void __launch_bounds__(128) prep_kernel(const float* __restrict__ pts,
                                                   const float* __restrict__ W) {
    int i = blockIdx.x * 128 + threadIdx.x;      // 0 .. 16383
    int o = i & (H - 1);
    int h = i >> 7;
    g_WT[i] = W[o * H + h];                      // WT[h*H+o] = W[o*H+h]
    if (i < NPTS) {
        float x = pts[3 * i], y = pts[3 * i + 1], z = pts[3 * i + 2];
        g_pts[i] = make_float4(x, y, z, x * x + y * y + z * z);
    }
}

// ---------------------------------------------------------------------------
// Table build: row r corresponds to d_idx = (r-1)*0.1.
// g_o(d) = b[o] + sum_k sin(d*f_k)*W[o,2k] + cos(d*f_k)*W[o,2k+1],
// f_k = exp(2k * (-ln(10000)/128)).
// 64 threads compute the interleaved sincos embedding into smem; all 128
// threads then do a coalesced dot with WT.
// ---------------------------------------------------------------------------
__global__ void __launch_bounds__(128) build_table(const float* __restrict__ b) {
    __shared__ float emb[H];
    int row = blockIdx.x;
    int t = threadIdx.x;
    float d = (row - 1) * 0.1f;
    if (t < 64) {
        const float coef = -0.07195578415606394f;   // -ln(10000)/128
        float f = expf((float)(2 * t) * coef);
        float s, c;
        sincosf(d * f, &s, &c);                     // accurate sincos (table only)
        emb[2 * t]     = s;
        emb[2 * t + 1] = c;
    }
    __syncthreads();
    float acc = b[t];
    #pragma unroll 16
    for (int h = 0; h < H; h++)
        acc = fmaf(emb[h], g_WT[h * H + t], acc);
    g_table[row * H + t] = acc;
}

// ---------------------------------------------------------------------------
// Pair kernel: one warp per (n,m) pair with n <= m; quadratic interp of the
// table; write out[n,m,:] and mirror out[m,n,:] (distance is symmetric).
// ---------------------------------------------------------------------------
__device__ __forceinline__ int tri_base(int n) {
    // first linear index of row n in the upper-triangle enumeration
    return n * NPTS - (n * (n - 1)) / 2;
}

__global__ void __launch_bounds__(256) pair_kernel(float* __restrict__ out) {
    int gw = (int)((blockIdx.x * 256u + (unsigned)threadIdx.x) >> 5);
    if (gw >= TRI_TOTAL) return;
    int lane = threadIdx.x & 31;

    // Decode triangular index -> (n, m), n <= m.  fp32 guess + exact fixup.
    int n = (int)(1024.5f - sqrtf(1049600.25f - 2.0f * (float)gw));
    n = max(0, min(n, NPTS - 1));
    while (n < NPTS - 1 && tri_base(n + 1) <= gw) n++;
    while (n > 0 && tri_base(n) > gw) n--;
    int m = n + (gw - tri_base(n));

    // Distance exactly as the reference computes it: |x|^2 + |y|^2 - 2 x.y, clamped
    float4 pn = g_pts[n];
    float4 pm = g_pts[m];
    float xy = pn.x * pm.x + pn.y * pm.y + pn.z * pm.z;
    float sq = fmaxf(pn.w + pm.w - 2.0f * xy, 0.0f);
    float tc = sqrtf(sq) * 50.0f;                  // (1/0.2)/0.1: table coords
    tc = fminf(tc, (float)(TROWS - 3));

    float icf = rintf(tc);
    int   ic  = (int)icf;
    float fr  = tc - icf;                          // in [-0.5, 0.5]
    float wm = 0.5f * fr * (fr - 1.0f);
    float w0 = 1.0f - fr * fr;
    float wp = 0.5f * fr * (fr + 1.0f);

    // physical rows ic, ic+1, ic+2  <->  coords ic-1, ic, ic+1
    const float4* rm = (const float4*)(g_table + (size_t)ic * H);
    const float4* r0 = rm + (H / 4);
    const float4* rp = r0 + (H / 4);
    float4 a  = rm[lane];
    float4 bb = r0[lane];
    float4 c  = rp[lane];
    float4 res;
    res.x = fmaf(wm, a.x, fmaf(w0, bb.x, wp * c.x));
    res.y = fmaf(wm, a.y, fmaf(w0, bb.y, wp * c.y));
    res.z = fmaf(wm, a.z, fmaf(w0, bb.z, wp * c.z));
    res.w = fmaf(wm, a.w, fmaf(w0, bb.w, wp * c.w));

    float4* out4 = (float4*)out;
    size_t p1 = ((size_t)n * NPTS + m) * (H / 4);
    out4[p1 + lane] = res;
    if (m != n) {
        size_t p2 = ((size_t)m * NPTS + n) * (H / 4);
        out4[p2 + lane] = res;
    }
}

// ---------------------------------------------------------------------------
extern "C" void kernel_launch(void* const* d_in, const int* in_sizes, int n_in,
                              void* d_out, int out_size) {
    const float* points = (const float*)d_in[0];
    const float* W      = (const float*)d_in[1];
    const float* b      = (const float*)d_in[2];
    float* out = (float*)d_out;

    prep_kernel<<<(H * H) / 128, 128>>>(points, W);
    build_table<<<TROWS, 128>>>(b);

    int blocks = (TRI_TOTAL * 32 + 255) / 256;     // 65600
    pair_kernel<<<blocks, 256>>>(out);
}